// round 1
// baseline (speedup 1.0000x reference)
#include <cuda_runtime.h>

// EncoderGRU: B=16384, T=512, I=4, H=64, gate order (r,z,n), h0 = 0.
// out = h_T  [B, H] fp32.
//
// Strategy: warp processes NB=4 batch elements over all 512 steps (recurrence is
// batch-private, no inter-CTA sync). Lane l owns hidden units {l, l+32} packed as
// f32x2. W_hh transposed in SMEM, broadcast-read per k and amortized over 4 batches
// with packed fma.rn.f32x2 (Blackwell 2x-FP32 path). Gates via __expf (MUFU), h'
// = z*(h-n)+n.

#define GRU_T 512
#define NB 4

using u64 = unsigned long long;

__device__ __forceinline__ u64 pk2(float a, float b) {
    u64 r; asm("mov.b64 %0,{%1,%2};" : "=l"(r) : "f"(a), "f"(b)); return r;
}
__device__ __forceinline__ void upk2(u64 v, float &a, float &b) {
    asm("mov.b64 {%0,%1},%2;" : "=f"(a), "=f"(b) : "l"(v));
}
__device__ __forceinline__ u64 fma2(u64 a, u64 b, u64 c) {
    u64 d; asm("fma.rn.f32x2 %0,%1,%2,%3;" : "=l"(d) : "l"(a), "l"(b), "l"(c)); return d;
}
__device__ __forceinline__ u64 add2(u64 a, u64 b) {
    u64 d; asm("add.rn.f32x2 %0,%1,%2;" : "=l"(d) : "l"(a), "l"(b)); return d;
}
// sigmoid(x) = 1/(1+exp(-x)); safe at extremes: exp->inf => rcp->0 => 0; exp->0 => 1.
__device__ __forceinline__ float sigf(float x) {
    return __fdividef(1.0f, 1.0f + __expf(-x));
}
// tanh(x) = 1 - 2/(exp(2x)+1); safe at extremes (no inf/inf).
__device__ __forceinline__ float tanhf_fast(float x) {
    return 1.0f - __fdividef(2.0f, __expf(2.0f * x) + 1.0f);
}

__global__ __launch_bounds__(256, 2)
void gru_kernel(const float* __restrict__ x,
                const float* __restrict__ w_ih,
                const float* __restrict__ w_hh,
                const float* __restrict__ b_ih,
                const float* __restrict__ b_hh,
                float* __restrict__ out)
{
    // wt[k][gate][lane] = { w_hh[gate*64 + lane][k], w_hh[gate*64 + lane + 32][k] }
    // 64*3*32*8B = 48 KB (static limit exactly). Lane-consecutive float2 -> conflict-free LDS.64.
    __shared__ float2 wt[64][3][32];

    const int tid = threadIdx.x;
    for (int idx = tid; idx < 64 * 96; idx += 256) {
        int k = idx / 96;
        int r = idx % 96;
        int g = r >> 5;
        int l = r & 31;
        wt[k][g][l] = make_float2(w_hh[(g * 64 + l) * 64 + k],
                                  w_hh[(g * 64 + l + 32) * 64 + k]);
    }
    __syncthreads();

    const int lane = tid & 31;
    const int warp = tid >> 5;
    const int b0 = (blockIdx.x * 8 + warp) * NB;

    // W_ih rows for this lane's two units, packed per (gate, input col): 12 x f32x2.
    u64 wih2[3][4];
#pragma unroll
    for (int g = 0; g < 3; g++)
#pragma unroll
        for (int c = 0; c < 4; c++)
            wih2[g][c] = pk2(w_ih[(g * 64 + lane) * 4 + c],
                             w_ih[(g * 64 + lane + 32) * 4 + c]);

    // Biases: r,z combined (b_ih + b_hh) on x-side accumulator; n split (b_in on x-side,
    // b_hn on h-side, since n = tanh(xn + b_in + r*(hn + b_hn))).
    const u64 br  = pk2(b_ih[lane]      + b_hh[lane],      b_ih[lane + 32] + b_hh[lane + 32]);
    const u64 bz  = pk2(b_ih[64 + lane] + b_hh[64 + lane], b_ih[96 + lane] + b_hh[96 + lane]);
    const u64 bnx = pk2(b_ih[128 + lane], b_ih[160 + lane]);
    const u64 bnh = pk2(b_hh[128 + lane], b_hh[160 + lane]);

    float h0[NB], h1[NB];  // h0[q] = h[lane], h1[q] = h[lane+32] for batch b0+q
#pragma unroll
    for (int q = 0; q < NB; q++) { h0[q] = 0.0f; h1[q] = 0.0f; }

    const float4* __restrict__ xp = (const float4*)x;  // I=4 floats = one float4/step

    for (int t = 0; t < GRU_T; t++) {
        // Issue x loads first; consumed only after the ~1500-instr k-loops (latency cover).
        float4 xv[NB];
#pragma unroll
        for (int q = 0; q < NB; q++)
            xv[q] = xp[(size_t)(b0 + q) * GRU_T + t];

        // h-side gate pre-activations: gh = W_hh h (+ b_hn for n-gate)
        u64 ahr[NB], ahz[NB], ahn[NB];
#pragma unroll
        for (int q = 0; q < NB; q++) { ahr[q] = 0ULL; ahz[q] = 0ULL; ahn[q] = bnh; }

#pragma unroll 8
        for (int k = 0; k < 32; k++) {
            u64 wr = *(const u64*)&wt[k][0][lane];
            u64 wz = *(const u64*)&wt[k][1][lane];
            u64 wn = *(const u64*)&wt[k][2][lane];
#pragma unroll
            for (int q = 0; q < NB; q++) {
                float hk = __shfl_sync(0xffffffffu, h0[q], k);
                u64 hs = pk2(hk, hk);
                ahr[q] = fma2(wr, hs, ahr[q]);
                ahz[q] = fma2(wz, hs, ahz[q]);
                ahn[q] = fma2(wn, hs, ahn[q]);
            }
        }
#pragma unroll 8
        for (int k = 0; k < 32; k++) {
            u64 wr = *(const u64*)&wt[32 + k][0][lane];
            u64 wz = *(const u64*)&wt[32 + k][1][lane];
            u64 wn = *(const u64*)&wt[32 + k][2][lane];
#pragma unroll
            for (int q = 0; q < NB; q++) {
                float hk = __shfl_sync(0xffffffffu, h1[q], k);
                u64 hs = pk2(hk, hk);
                ahr[q] = fma2(wr, hs, ahr[q]);
                ahz[q] = fma2(wz, hs, ahz[q]);
                ahn[q] = fma2(wn, hs, ahn[q]);
            }
        }

        // x-side pre-activations + gates + state update
#pragma unroll
        for (int q = 0; q < NB; q++) {
            u64 axr = br, axz = bz, axn = bnx;
            float xc[4] = { xv[q].x, xv[q].y, xv[q].z, xv[q].w };
#pragma unroll
            for (int c = 0; c < 4; c++) {
                u64 xs = pk2(xc[c], xc[c]);
                axr = fma2(wih2[0][c], xs, axr);
                axz = fma2(wih2[1][c], xs, axz);
                axn = fma2(wih2[2][c], xs, axn);
            }

            float r0, r1, z0, z1, nx0, nx1, nh0, nh1;
            upk2(add2(axr, ahr[q]), r0, r1);
            upk2(add2(axz, ahz[q]), z0, z1);
            upk2(axn, nx0, nx1);
            upk2(ahn[q], nh0, nh1);

            r0 = sigf(r0); r1 = sigf(r1);
            z0 = sigf(z0); z1 = sigf(z1);

            float n0 = tanhf_fast(fmaf(r0, nh0, nx0));
            float n1 = tanhf_fast(fmaf(r1, nh1, nx1));

            // h' = (1-z)*n + z*h = z*(h-n) + n
            h0[q] = fmaf(z0, h0[q] - n0, n0);
            h1[q] = fmaf(z1, h1[q] - n1, n1);
        }
    }

#pragma unroll
    for (int q = 0; q < NB; q++) {
        out[(size_t)(b0 + q) * 64 + lane]      = h0[q];
        out[(size_t)(b0 + q) * 64 + lane + 32] = h1[q];
    }
}

extern "C" void kernel_launch(void* const* d_in, const int* in_sizes, int n_in,
                              void* d_out, int out_size)
{
    const float* x    = (const float*)d_in[0];
    const float* w_ih = (const float*)d_in[1];
    const float* w_hh = (const float*)d_in[2];
    const float* b_ih = (const float*)d_in[3];
    const float* b_hh = (const float*)d_in[4];
    float* out = (float*)d_out;

    // 16384 batch / (8 warps * NB=4) = 512 CTAs of 256 threads.
    gru_kernel<<<512, 256>>>(x, w_ih, w_hh, b_ih, b_hh, out);
}

// round 4
// speedup vs baseline: 1.3194x; 1.3194x over previous
#include <cuda_runtime.h>
#include <cstdint>

// EncoderGRU B=16384 T=512 I=4 H=64 — f32x2 FMA path, MIO-minimized.
// 148 CTAs x 512 thr (16 warps), 1 CTA/SM, one wave. Warp owns NB=7 batches
// for all 512 steps (batch-private recurrence; only __syncwarp per step).
// Lane l owns hidden units {l, l+32} packed as f32x2.
//   - h state in smem (double-buffered), read via LDS.64 *broadcast* (no SHFL)
//   - W_hh in smem: r,z packed per-k as float4 (1 LDS.128), n packed 2k/float4
//   - W_ih / biases in smem, loaded into short-lived temps per step (reg diet)
// Gate math identical to the proven rel_err=3e-7 kernel (expf-based).

#define T_STEPS 512
#define NB      7
#define THREADS 512
#define NW      16
#define BATCH   16384

using u64 = unsigned long long;

// dynamic smem offsets (bytes)
#define OFF_WRZ 0u                      // float4[64][32]   32768
#define OFF_WN2 32768u                  // float4[32][32]   16384
#define OFF_H0  49152u                  // float[NW*NB*64]  28672
#define OFF_H1  77824u                  // float[NW*NB*64]  28672
#define OFF_WIH 106496u                 // u64[12][32]       3072
#define OFF_BIA 109568u                 // u64[4][32]        1024
#define SMEM_TOTAL 110592

__device__ __forceinline__ u64 pk2(float a, float b) {
    u64 r; asm("mov.b64 %0,{%1,%2};" : "=l"(r) : "f"(a), "f"(b)); return r;
}
__device__ __forceinline__ void upk2(u64 v, float &a, float &b) {
    asm("mov.b64 {%0,%1},%2;" : "=f"(a), "=f"(b) : "l"(v));
}
__device__ __forceinline__ u64 fma2(u64 a, u64 b, u64 c) {
    u64 d; asm("fma.rn.f32x2 %0,%1,%2,%3;" : "=l"(d) : "l"(a), "l"(b), "l"(c)); return d;
}
__device__ __forceinline__ u64 add2(u64 a, u64 b) {
    u64 d; asm("add.rn.f32x2 %0,%1,%2;" : "=l"(d) : "l"(a), "l"(b)); return d;
}
__device__ __forceinline__ float sigf(float x) {               // exact-enough sigmoid
    return __fdividef(1.0f, 1.0f + __expf(-x));
}
__device__ __forceinline__ float tanhf_fast(float x) {         // 1 - 2/(e^2x+1)
    return 1.0f - __fdividef(2.0f, __expf(2.0f * x) + 1.0f);
}

__global__ __launch_bounds__(THREADS, 1)
void gru_v3(const float* __restrict__ x, const float* __restrict__ w_ih,
            const float* __restrict__ w_hh, const float* __restrict__ b_ih,
            const float* __restrict__ b_hh, float* __restrict__ out)
{
    extern __shared__ char sm[];
    float4* WRZ  = (float4*)(sm + OFF_WRZ);    // WRZ[k*32+l] = {r_l, r_l32, z_l, z_l32} at col k
    float4* WN2  = (float4*)(sm + OFF_WN2);    // WN2[c*32+l] = {n_l, n_l32}@k=2c, {..}@k=2c+1
    float*  Hbuf[2] = { (float*)(sm + OFF_H0), (float*)(sm + OFF_H1) };
    u64*    WIH  = (u64*)(sm + OFF_WIH);       // WIH[(g*4+c)*32+l] = {wih[g*64+l][c], wih[g*64+l+32][c]}
    u64*    BIA  = (u64*)(sm + OFF_BIA);       // 0:br 1:bz 2:bnx 3:bnh (packed l,l+32)

    const int tid = threadIdx.x, lane = tid & 31, warp = tid >> 5;

    // ---- one-time smem fill ----
    for (int i = tid; i < 64 * 32; i += THREADS) {
        int k = i >> 5, l = i & 31;
        WRZ[i] = make_float4(w_hh[l * 64 + k],        w_hh[(l + 32) * 64 + k],
                             w_hh[(64 + l) * 64 + k], w_hh[(96 + l) * 64 + k]);
    }
    for (int i = tid; i < 32 * 32; i += THREADS) {
        int c = i >> 5, l = i & 31;
        WN2[i] = make_float4(w_hh[(128 + l) * 64 + 2 * c],     w_hh[(160 + l) * 64 + 2 * c],
                             w_hh[(128 + l) * 64 + 2 * c + 1], w_hh[(160 + l) * 64 + 2 * c + 1]);
    }
    for (int i = tid; i < NW * NB * 64; i += THREADS) Hbuf[0][i] = 0.0f;  // h(0) = 0
    for (int i = tid; i < 12 * 32; i += THREADS) {
        int j = i >> 5, l = i & 31, g = j >> 2, c = j & 3;
        WIH[i] = pk2(w_ih[(g * 64 + l) * 4 + c], w_ih[(g * 64 + l + 32) * 4 + c]);
    }
    if (tid < 32) {
        BIA[tid]      = pk2(b_ih[tid] + b_hh[tid],           b_ih[tid + 32] + b_hh[tid + 32]);
        BIA[32 + tid] = pk2(b_ih[64 + tid] + b_hh[64 + tid], b_ih[96 + tid] + b_hh[96 + tid]);
        BIA[64 + tid] = pk2(b_ih[128 + tid], b_ih[160 + tid]);
        BIA[96 + tid] = pk2(b_hh[128 + tid], b_hh[160 + tid]);
    }
    __syncthreads();   // the only CTA-wide sync

    // ---- per-warp geometry ----
    const int  wg    = blockIdx.x * NW + warp;       // global warp id
    const int  bbase = wg * NB;
    const int  hoff  = warp * (NB * 64);             // this warp's slab in Hbuf
    const float4* __restrict__ xp = (const float4*)x;

    // lane q (<NB) holds x(batch bbase+q, t); clamp OOB batches (stores guarded later)
    int bq = bbase + lane;
    if (bq >= BATCH) bq = BATCH - 1;
    float4 xq = make_float4(0.f, 0.f, 0.f, 0.f);
    if (lane < NB) xq = xp[(size_t)bq * T_STEPS + 0];

    const u64 Z = 0ULL;

    for (int t = 0; t < T_STEPS; t++) {
        const float* __restrict__ hrd = Hbuf[t & 1]         + hoff;
        float*       __restrict__ hwr = Hbuf[(t & 1) ^ 1]   + hoff;

        // ---- x-side fold: acc = W_ih x (+ bias later, from smem) ----
        u64 w[12];
#pragma unroll
        for (int j = 0; j < 12; j++) w[j] = WIH[j * 32 + lane];

        u64 ar[NB], az[NB], axn[NB], an[NB];
#pragma unroll
        for (int q = 0; q < NB; q++) {
            float x0 = __shfl_sync(0xffffffffu, xq.x, q);
            float x1 = __shfl_sync(0xffffffffu, xq.y, q);
            float x2 = __shfl_sync(0xffffffffu, xq.z, q);
            float x3 = __shfl_sync(0xffffffffu, xq.w, q);
            u64 s0 = pk2(x0, x0), s1 = pk2(x1, x1), s2 = pk2(x2, x2), s3 = pk2(x3, x3);
            ar[q]  = fma2(w[0], s0, fma2(w[1], s1, fma2(w[2],  s2, fma2(w[3],  s3, Z))));
            az[q]  = fma2(w[4], s0, fma2(w[5], s1, fma2(w[6],  s2, fma2(w[7],  s3, Z))));
            axn[q] = fma2(w[8], s0, fma2(w[9], s1, fma2(w[10], s2, fma2(w[11], s3, Z))));
            an[q]  = Z;
        }

        // prefetch x(t+1) under the k-loop's latency
        if (lane < NB && t + 1 < T_STEPS)
            xq = xp[(size_t)bq * T_STEPS + (t + 1)];

        // ---- h-side matvec: 64 k in 32 chunks of 2 ----
        const ulonglong2* __restrict__ WRZ2 = (const ulonglong2*)WRZ;
        const ulonglong2* __restrict__ WN2u = (const ulonglong2*)WN2;
#pragma unroll 4
        for (int c = 0; c < 32; c++) {
            float2 hq[NB];
#pragma unroll
            for (int q = 0; q < NB; q++)                      // broadcast reads
                hq[q] = *(const float2*)(hrd + q * 64 + 2 * c);
            ulonglong2 la = WRZ2[(2 * c)     * 32 + lane];    // k=2c   : {wr, wz}
            ulonglong2 lb = WRZ2[(2 * c + 1) * 32 + lane];    // k=2c+1 : {wr, wz}
            ulonglong2 ln = WN2u[c * 32 + lane];              // {wn@2c, wn@2c+1}
#pragma unroll
            for (int q = 0; q < NB; q++) {
                u64 s = pk2(hq[q].x, hq[q].x);
                ar[q] = fma2(la.x, s, ar[q]);
                az[q] = fma2(la.y, s, az[q]);
                an[q] = fma2(ln.x, s, an[q]);
            }
#pragma unroll
            for (int q = 0; q < NB; q++) {
                u64 s = pk2(hq[q].y, hq[q].y);
                ar[q] = fma2(lb.x, s, ar[q]);
                az[q] = fma2(lb.y, s, az[q]);
                an[q] = fma2(ln.y, s, an[q]);
            }
        }

        // ---- epilogue: gates + state update ----
        const u64 br  = BIA[lane];
        const u64 bz  = BIA[32 + lane];
        const u64 bnx = BIA[64 + lane];
        const u64 bnh = BIA[96 + lane];
#pragma unroll
        for (int q = 0; q < NB; q++) {
            float r0, r1, z0, z1, hn0, hn1, xn0, xn1;
            upk2(add2(ar[q], br), r0, r1);
            upk2(add2(az[q], bz), z0, z1);
            upk2(add2(an[q], bnh), hn0, hn1);
            upk2(add2(axn[q], bnx), xn0, xn1);

            r0 = sigf(r0); r1 = sigf(r1);
            z0 = sigf(z0); z1 = sigf(z1);
            float n0 = tanhf_fast(fmaf(r0, hn0, xn0));
            float n1 = tanhf_fast(fmaf(r1, hn1, xn1));

            float ho0 = hrd[q * 64 + lane];                   // old h (broadcast-free, lane-indexed)
            float ho1 = hrd[q * 64 + lane + 32];
            hwr[q * 64 + lane]      = fmaf(z0, ho0 - n0, n0); // h' = z*(h-n)+n
            hwr[q * 64 + lane + 32] = fmaf(z1, ho1 - n1, n1);
        }
        __syncwarp();
    }

    // final h is in Hbuf[T_STEPS & 1] = Hbuf[0]
    const float* __restrict__ hfin = Hbuf[T_STEPS & 1] + hoff;
#pragma unroll
    for (int q = 0; q < NB; q++) {
        int b = bbase + q;
        if (b < BATCH) {
            out[(size_t)b * 64 + lane]      = hfin[q * 64 + lane];
            out[(size_t)b * 64 + lane + 32] = hfin[q * 64 + lane + 32];
        }
    }
}

extern "C" void kernel_launch(void* const* d_in, const int* in_sizes, int n_in,
                              void* d_out, int out_size)
{
    const float* x    = (const float*)d_in[0];
    const float* w_ih = (const float*)d_in[1];
    const float* w_hh = (const float*)d_in[2];
    const float* b_ih = (const float*)d_in[3];
    const float* b_hh = (const float*)d_in[4];
    float* out = (float*)d_out;

    cudaFuncSetAttribute(gru_v3, cudaFuncAttributeMaxDynamicSharedMemorySize, SMEM_TOTAL);
    gru_v3<<<148, THREADS, SMEM_TOTAL>>>(x, w_ih, w_hh, b_ih, b_hh, out);
}

// round 5
// speedup vs baseline: 1.5163x; 1.1493x over previous
#include <cuda_runtime.h>
#include <cstdint>

// EncoderGRU B=16384 T=512 I=4 H=64 — tf32 mma.sync persistent recurrence.
// 128 CTAs x 128 thr (4 warps, 1/SMSP). Warp owns 32 batches (2x m16) for all
// 512 steps. Per step: D = [h | x] x [W_hh ; W_ih] via m16n8k8 tf32 MMAs with
// hi/lo split (3 terms). D tiles: r(nt 0..7), z(8..15), hn(16..23), xn(sep).
// Gates computed on D frags in regs; h' -> padded smem (stride 68) -> A frags.

#define T_STEPS 512
#define THREADS 128
#define HP 68   // padded h row stride (floats): conflict-free A-frag loads

// dynamic smem offsets (bytes)
#define OFF_BB   0u        // ulonglong2[24 nt][9 kt][32 lane]  110592
#define OFF_BXN  110592u   // ulonglong2[8 nt][32 lane]           4096
#define OFF_HS   114688u   // float[4 warps][32][HP]             34816
#define OFF_BRZ  149504u   // float[128]
#define OFF_BNH  150016u   // float[64]
#define OFF_BNX  150272u   // float[64]
#define SMEM_TOTAL 150528

__device__ __forceinline__ uint32_t tf32hi(float x) {
    uint32_t u; asm("cvt.rna.tf32.f32 %0, %1;" : "=r"(u) : "f"(x)); return u;
}
__device__ __forceinline__ void tf32split(float x, uint32_t& hi, uint32_t& lo) {
    hi = tf32hi(x);
    lo = tf32hi(x - __uint_as_float(hi));
}
__device__ __forceinline__ void mma8(float* d, const uint32_t* a, uint32_t b0, uint32_t b1) {
    asm("mma.sync.aligned.m16n8k8.row.col.f32.tf32.tf32.f32 "
        "{%0,%1,%2,%3}, {%4,%5,%6,%7}, {%8,%9}, {%0,%1,%2,%3};"
        : "+f"(d[0]), "+f"(d[1]), "+f"(d[2]), "+f"(d[3])
        : "r"(a[0]), "r"(a[1]), "r"(a[2]), "r"(a[3]), "r"(b0), "r"(b1));
}
__device__ __forceinline__ float sigf(float x) {
    return __fdividef(1.0f, 1.0f + __expf(-x));
}
__device__ __forceinline__ float tanhf_fast(float x) {
    return 1.0f - __fdividef(2.0f, __expf(2.0f * x) + 1.0f);
}
#define LO32(u) ((uint32_t)(u))
#define HI32(u) ((uint32_t)((u) >> 32))

__global__ __launch_bounds__(THREADS, 1)
void gru_mma(const float* __restrict__ x, const float* __restrict__ w_ih,
             const float* __restrict__ w_hh, const float* __restrict__ b_ih,
             const float* __restrict__ b_hh, float* __restrict__ out)
{
    extern __shared__ char sm[];
    ulonglong2* BB  = (ulonglong2*)(sm + OFF_BB);
    ulonglong2* BXN = (ulonglong2*)(sm + OFF_BXN);
    float* HS  = (float*)(sm + OFF_HS);
    float* BRZ = (float*)(sm + OFF_BRZ);
    float* BNH = (float*)(sm + OFF_BNH);
    float* BNX = (float*)(sm + OFF_BNX);

    const int tid = threadIdx.x, lane = tid & 31, warp = tid >> 5;

    // ================= one-time init =================
    // BB[nt][kt][lane]: B-frag entry for tile (nt, kt). Frag-lane le covers
    // n = nt*8 + le/4, k0 = kt*8 + le%4, k1 = k0+4.
    //   .x = {bhi(k0), bhi(k1)},  .y = {blo(k0), blo(k1)}
    // B[k][n]: k<64 -> w_hh[n][k]; nt<16 & k in 64..67 -> w_ih[n][k-64] (hi+lo);
    //          nt<16 & k in 68..71 -> dup w_ih_hi[n][k-68], lo=0; else 0.
    for (int idx = tid; idx < 24 * 9 * 32; idx += THREADS) {
        int nt = idx / 288, rem = idx % 288, kt = rem / 32, le = rem & 31;
        int n = nt * 8 + (le >> 2);
        uint32_t h01[2], l01[2];
#pragma unroll
        for (int half = 0; half < 2; half++) {
            int k = kt * 8 + (le & 3) + 4 * half;
            uint32_t hi = 0, lo = 0;
            if (k < 64) {
                tf32split(w_hh[n * 64 + k], hi, lo);
            } else if (nt < 16) {
                int c = k - 64;
                if (c < 4) tf32split(w_ih[n * 4 + c], hi, lo);
                else { uint32_t l_; tf32split(w_ih[n * 4 + c - 4], hi, l_); lo = 0; }
            }
            h01[half] = hi; l01[half] = lo;
        }
        BB[idx].x = (uint64_t)h01[0] | ((uint64_t)h01[1] << 32);
        BB[idx].y = (uint64_t)l01[0] | ((uint64_t)l01[1] << 32);
    }
    // BXN[nt'][lane]: xn tiles, n = 128 + nt'*8 + le/4, k rows 0..3 = wih_hi/lo,
    // rows 4..7 = dup wih_hi (lo = 0).
    for (int idx = tid; idx < 8 * 32; idx += THREADS) {
        int nt = idx >> 5, le = idx & 31;
        int n = 128 + nt * 8 + (le >> 2), c = le & 3;
        uint32_t hi, lo;
        tf32split(w_ih[n * 4 + c], hi, lo);
        BXN[idx].x = (uint64_t)hi | ((uint64_t)hi << 32);
        BXN[idx].y = (uint64_t)lo;   // high word 0
    }
    for (int idx = tid; idx < 4 * 32 * HP; idx += THREADS) HS[idx] = 0.0f;
    for (int idx = tid; idx < 128; idx += THREADS) BRZ[idx] = b_ih[idx] + b_hh[idx];
    if (tid < 64) { BNH[tid] = b_hh[128 + tid]; BNX[tid] = b_ih[128 + tid]; }
    __syncthreads();

    // ================= per-warp geometry =================
    const int base = (blockIdx.x * 4 + warp) * 32;     // batch base
    float* hs = HS + warp * 32 * HP;
    const int lq = lane >> 2, c = lane & 3;            // frag row-group, col-in-group
    const int u0 = 2 * c;                              // D col pair base within tile

    // x(t) gmem addresses: xq[i] = x[base + lq + 8i][t][c]
    const float* __restrict__ xb = x + ((size_t)(base + lq) * T_STEPS) * 4 + c;

    float xq[4];
#pragma unroll
    for (int i = 0; i < 4; i++) xq[i] = xb[(size_t)(8 * i) * T_STEPS * 4];

    uint32_t Ah[2][8][4], Al[2][8][4], Ax[2][4];

    for (int t = 0; t < T_STEPS; t++) {
        // ---- A frags from h smem (zero at t=0) + split ----
#pragma unroll
        for (int mh = 0; mh < 2; mh++) {
            const float* hr = hs + (mh * 16 + lq) * HP;
#pragma unroll
            for (int kt = 0; kt < 8; kt++) {
                tf32split(hr[kt * 8 + c],            Ah[mh][kt][0], Al[mh][kt][0]);
                tf32split(hr[8 * HP + kt * 8 + c],   Ah[mh][kt][1], Al[mh][kt][1]);
                tf32split(hr[kt * 8 + 4 + c],        Ah[mh][kt][2], Al[mh][kt][2]);
                tf32split(hr[8 * HP + kt * 8 + 4 + c], Ah[mh][kt][3], Al[mh][kt][3]);
            }
        }
        // ---- x frag (A cols 64..71 = x_hi|x_lo); Alo for this ktile is 0 ----
#pragma unroll
        for (int mh = 0; mh < 2; mh++) {
            tf32split(xq[2 * mh],     Ax[mh][0], Ax[mh][2]);
            tf32split(xq[2 * mh + 1], Ax[mh][1], Ax[mh][3]);
        }
        // prefetch x(t+1) under MMA latency
        if (t + 1 < T_STEPS) {
            const float* xn = xb + (size_t)(t + 1) * 4;
#pragma unroll
            for (int i = 0; i < 4; i++) xq[i] = xn[(size_t)(8 * i) * T_STEPS * 4];
        }

        // ---- per unit-block j: 8 units, all 32 batches ----
#pragma unroll 1
        for (int j = 0; j < 8; j++) {
            float dr[2][4] = {}, dz[2][4] = {}, dn[2][4] = {}, dx[2][4] = {};
            const ulonglong2* Br = BB + (j * 9) * 32 + lane;
            const ulonglong2* Bz = BB + ((8 + j) * 9) * 32 + lane;
            const ulonglong2* Bn = BB + ((16 + j) * 9) * 32 + lane;
#pragma unroll
            for (int kt = 0; kt < 8; kt++) {
                ulonglong2 br = Br[kt * 32], bz = Bz[kt * 32], bn = Bn[kt * 32];
#pragma unroll
                for (int mh = 0; mh < 2; mh++) {
                    mma8(dr[mh], Ah[mh][kt], LO32(br.x), HI32(br.x));
                    mma8(dz[mh], Ah[mh][kt], LO32(bz.x), HI32(bz.x));
                    mma8(dn[mh], Ah[mh][kt], LO32(bn.x), HI32(bn.x));
                    mma8(dr[mh], Al[mh][kt], LO32(br.x), HI32(br.x));
                    mma8(dz[mh], Al[mh][kt], LO32(bz.x), HI32(bz.x));
                    mma8(dn[mh], Al[mh][kt], LO32(bn.x), HI32(bn.x));
                    mma8(dr[mh], Ah[mh][kt], LO32(br.y), HI32(br.y));
                    mma8(dz[mh], Ah[mh][kt], LO32(bz.y), HI32(bz.y));
                    mma8(dn[mh], Ah[mh][kt], LO32(bn.y), HI32(bn.y));
                }
            }
            {   // kt = 8: x columns for r,z; xn tile
                ulonglong2 br = Br[8 * 32], bz = Bz[8 * 32], bx = BXN[j * 32 + lane];
#pragma unroll
                for (int mh = 0; mh < 2; mh++) {
                    mma8(dr[mh], Ax[mh], LO32(br.x), HI32(br.x));
                    mma8(dz[mh], Ax[mh], LO32(bz.x), HI32(bz.x));
                    mma8(dx[mh], Ax[mh], LO32(bx.x), HI32(bx.x));
                    mma8(dr[mh], Ax[mh], LO32(br.y), HI32(br.y));
                    mma8(dz[mh], Ax[mh], LO32(bz.y), HI32(bz.y));
                    mma8(dx[mh], Ax[mh], LO32(bx.y), HI32(bx.y));
                }
            }
            // ---- epilogue for units j*8+u0, +1 ----
            float2 b_r = *(const float2*)(BRZ + j * 8 + u0);
            float2 b_z = *(const float2*)(BRZ + 64 + j * 8 + u0);
            float2 b_h = *(const float2*)(BNH + j * 8 + u0);
            float2 b_x = *(const float2*)(BNX + j * 8 + u0);
#pragma unroll
            for (int mh = 0; mh < 2; mh++) {
                float* ha = hs + (mh * 16 + lq) * HP + j * 8 + u0;
                float2 hoa = *(const float2*)ha;
                float2 hob = *(const float2*)(ha + 8 * HP);
                float hn0, hn1, hn2, hn3;
                {
                    float r = sigf(dr[mh][0] + b_r.x), z = sigf(dz[mh][0] + b_z.x);
                    float n = tanhf_fast(fmaf(r, dn[mh][0] + b_h.x, dx[mh][0] + b_x.x));
                    hn0 = fmaf(z, hoa.x - n, n);
                }
                {
                    float r = sigf(dr[mh][1] + b_r.y), z = sigf(dz[mh][1] + b_z.y);
                    float n = tanhf_fast(fmaf(r, dn[mh][1] + b_h.y, dx[mh][1] + b_x.y));
                    hn1 = fmaf(z, hoa.y - n, n);
                }
                {
                    float r = sigf(dr[mh][2] + b_r.x), z = sigf(dz[mh][2] + b_z.x);
                    float n = tanhf_fast(fmaf(r, dn[mh][2] + b_h.x, dx[mh][2] + b_x.x));
                    hn2 = fmaf(z, hob.x - n, n);
                }
                {
                    float r = sigf(dr[mh][3] + b_r.y), z = sigf(dz[mh][3] + b_z.y);
                    float n = tanhf_fast(fmaf(r, dn[mh][3] + b_h.y, dx[mh][3] + b_x.y));
                    hn3 = fmaf(z, hob.y - n, n);
                }
                *(float2*)ha            = make_float2(hn0, hn1);
                *(float2*)(ha + 8 * HP) = make_float2(hn2, hn3);
            }
        }
        __syncwarp();
    }

    // ---- output ----
#pragma unroll
    for (int idx = lane; idx < 32 * 16; idx += 32) {
        int b = idx >> 4, q = idx & 15;
        float4 v = *(const float4*)(hs + b * HP + q * 4);
        ((float4*)out)[(size_t)(base + b) * 16 + q] = v;
    }
}

extern "C" void kernel_launch(void* const* d_in, const int* in_sizes, int n_in,
                              void* d_out, int out_size)
{
    const float* x    = (const float*)d_in[0];
    const float* w_ih = (const float*)d_in[1];
    const float* w_hh = (const float*)d_in[2];
    const float* b_ih = (const float*)d_in[3];
    const float* b_hh = (const float*)d_in[4];
    float* out = (float*)d_out;

    cudaFuncSetAttribute(gru_mma, cudaFuncAttributeMaxDynamicSharedMemorySize, SMEM_TOTAL);
    gru_mma<<<128, THREADS, SMEM_TOTAL>>>(x, w_ih, w_hh, b_ih, b_hh, out);
}

// round 6
// speedup vs baseline: 2.4026x; 1.5845x over previous
#include <cuda_runtime.h>
#include <cuda_bf16.h>
#include <cstdint>

// EncoderGRU B=16384 T=512 I=4 H=64 — bf16 m16n8k16 mma.sync recurrence.
// 128 CTAs x 256 thr (8 warps = 2/SMSP). Warp owns 16 batches (one m16 frag)
// for all 512 steps. h and W split hi+lo bf16; 3-term MMA (AhiBhi+AloBhi+AhiBlo)
// in fp32 accum. x (I=4) folded as one k16 tile: A=[xhi|xlo|xhi|0] vs
// B=[Whi|Whi|Wlo|0]. D tiles: r(nt0..7), z(8..15), hn(16..23), xn(separate).
// Gates on D frags in regs; h' -> padded smem (stride 72) -> next A frags.

#define T_STEPS 512
#define THREADS 256
#define HP 72   // h row stride (floats); HP%32==8 -> optimal 2-wavefront LDS.64

#define OFF_BB   0u        // ulonglong2[24 nt][4 kt][32]  49152
#define OFF_BX   49152u    // u64[16 nt][32]                4096  (x-tile B: r,z)
#define OFF_BXN  53248u    // u64[8 nt][32]                 2048  (x-tile B: xn)
#define OFF_HS   55296u    // float[8 warps][16][HP]       36864
#define OFF_BRZ  92160u    // float[128]
#define OFF_BNH  92672u    // float[64]
#define OFF_BNX  92928u    // float[64]
#define SMEM_TOTAL 93184

#define LO32(u) ((uint32_t)(u))
#define HI32(u) ((uint32_t)((u) >> 32))

__device__ __forceinline__ uint32_t pkb(__nv_bfloat16 a, __nv_bfloat16 b) {
    return (uint32_t)*(uint16_t*)&a | ((uint32_t)*(uint16_t*)&b << 16);
}
// split (a,b) into packed bf16 hi pair + bf16 lo (residual) pair
__device__ __forceinline__ void bsplit2(float a, float b, uint32_t& hi, uint32_t& lo) {
    __nv_bfloat16 ah = __float2bfloat16_rn(a), bh = __float2bfloat16_rn(b);
    __nv_bfloat16 al = __float2bfloat16_rn(a - __bfloat162float(ah));
    __nv_bfloat16 bl = __float2bfloat16_rn(b - __bfloat162float(bh));
    hi = pkb(ah, bh);
    lo = pkb(al, bl);
}
__device__ __forceinline__ void mma16(float* d, const uint32_t* a, uint32_t b0, uint32_t b1) {
    asm("mma.sync.aligned.m16n8k16.row.col.f32.bf16.bf16.f32 "
        "{%0,%1,%2,%3}, {%4,%5,%6,%7}, {%8,%9}, {%0,%1,%2,%3};"
        : "+f"(d[0]), "+f"(d[1]), "+f"(d[2]), "+f"(d[3])
        : "r"(a[0]), "r"(a[1]), "r"(a[2]), "r"(a[3]), "r"(b0), "r"(b1));
}
__device__ __forceinline__ float sigf(float x) {
    return __fdividef(1.0f, 1.0f + __expf(-x));
}
__device__ __forceinline__ float tanhf_fast(float x) {
    return 1.0f - __fdividef(2.0f, __expf(2.0f * x) + 1.0f);
}

__global__ __launch_bounds__(THREADS, 1)
void gru_bmma(const float* __restrict__ x, const float* __restrict__ w_ih,
              const float* __restrict__ w_hh, const float* __restrict__ b_ih,
              const float* __restrict__ b_hh, float* __restrict__ out)
{
    extern __shared__ char sm[];
    ulonglong2* BB  = (ulonglong2*)(sm + OFF_BB);
    uint64_t*   BX  = (uint64_t*)(sm + OFF_BX);
    uint64_t*   BXN = (uint64_t*)(sm + OFF_BXN);
    float* HS  = (float*)(sm + OFF_HS);
    float* BRZ = (float*)(sm + OFF_BRZ);
    float* BNH = (float*)(sm + OFF_BNH);
    float* BNX = (float*)(sm + OFF_BNX);

    const int tid = threadIdx.x, lane = tid & 31, warp = tid >> 5;

    // ================= one-time init =================
    // BB[nt][kt][lane]: B frag for tile n=nt*8+g, k pairs (kt*16+2c,+1) and (+8,+9).
    //   .x = {hi(k0,k0+1), hi(k8,k8+1)}  .y = same for lo residuals.
    for (int idx = tid; idx < 24 * 4 * 32; idx += THREADS) {
        int nt = idx >> 7, kt = (idx >> 5) & 3, le = idx & 31;
        int n = nt * 8 + (le >> 2), k0 = kt * 16 + 2 * (le & 3);
        uint32_t h01, l01, h89, l89;
        bsplit2(w_hh[n * 64 + k0],     w_hh[n * 64 + k0 + 1], h01, l01);
        bsplit2(w_hh[n * 64 + k0 + 8], w_hh[n * 64 + k0 + 9], h89, l89);
        BB[idx].x = (uint64_t)h01 | ((uint64_t)h89 << 32);
        BB[idx].y = (uint64_t)l01 | ((uint64_t)l89 << 32);
    }
    // x-tile B (k16 rows = [Whi(4) | Whi dup(4) | Wlo(4) | 0(4)]):
    //   b0 = Whi comps {2(c&1), 2(c&1)+1};  b1 = (c<2) ? Wlo comps : 0
    for (int idx = tid; idx < 16 * 32; idx += THREADS) {
        int nt = idx >> 5, le = idx & 31, c = le & 3;
        int n = nt * 8 + (le >> 2), cc = 2 * (c & 1);
        uint32_t hi, lo;
        bsplit2(w_ih[n * 4 + cc], w_ih[n * 4 + cc + 1], hi, lo);
        BX[idx] = (uint64_t)hi | ((uint64_t)((c < 2) ? lo : 0u) << 32);
    }
    for (int idx = tid; idx < 8 * 32; idx += THREADS) {
        int nt = idx >> 5, le = idx & 31, c = le & 3;
        int n = 128 + nt * 8 + (le >> 2), cc = 2 * (c & 1);
        uint32_t hi, lo;
        bsplit2(w_ih[n * 4 + cc], w_ih[n * 4 + cc + 1], hi, lo);
        BXN[idx] = (uint64_t)hi | ((uint64_t)((c < 2) ? lo : 0u) << 32);
    }
    for (int idx = tid; idx < 8 * 16 * HP; idx += THREADS) HS[idx] = 0.0f;
    for (int idx = tid; idx < 128; idx += THREADS) BRZ[idx] = b_ih[idx] + b_hh[idx];
    if (tid < 64) { BNH[tid] = b_hh[128 + tid]; BNX[tid] = b_ih[128 + tid]; }
    __syncthreads();

    // ================= per-warp geometry =================
    const int base = (blockIdx.x * 8 + warp) * 16;
    float* hs = HS + warp * 16 * HP;
    const int g = lane >> 2, c = lane & 3;
    const int u0 = 2 * c, cc = 2 * (c & 1);

    const float* __restrict__ xr0 = x + ((size_t)(base + g) * T_STEPS) * 4 + cc;
    const float* __restrict__ xr8 = x + ((size_t)(base + g + 8) * T_STEPS) * 4 + cc;
    float2 xq0 = *(const float2*)xr0;
    float2 xq8 = *(const float2*)xr8;

    uint32_t Ahi[4][4], Alo[4][4], Ax[4];

    for (int t = 0; t < T_STEPS; t++) {
        // ---- A frags from h smem (zero at t=0) ----
#pragma unroll
        for (int kt = 0; kt < 4; kt++) {
            const float* r0 = hs + g * HP + kt * 16 + u0;
            const float* r8 = r0 + 8 * HP;
            float2 v0 = *(const float2*)r0;
            float2 v8 = *(const float2*)r8;
            float2 w0 = *(const float2*)(r0 + 8);
            float2 w8 = *(const float2*)(r8 + 8);
            bsplit2(v0.x, v0.y, Ahi[kt][0], Alo[kt][0]);
            bsplit2(v8.x, v8.y, Ahi[kt][1], Alo[kt][1]);
            bsplit2(w0.x, w0.y, Ahi[kt][2], Alo[kt][2]);
            bsplit2(w8.x, w8.y, Ahi[kt][3], Alo[kt][3]);
        }
        // ---- x frag: A cols [xhi(4)|xlo(4)|xhi(4)|0(4)] ----
        {
            uint32_t xh0, xl0, xh8, xl8;
            bsplit2(xq0.x, xq0.y, xh0, xl0);
            bsplit2(xq8.x, xq8.y, xh8, xl8);
            Ax[0] = (c < 2) ? xh0 : xl0;
            Ax[1] = (c < 2) ? xh8 : xl8;
            Ax[2] = (c < 2) ? xh0 : 0u;
            Ax[3] = (c < 2) ? xh8 : 0u;
        }
        if (t + 1 < T_STEPS) {   // prefetch under MMA latency
            xq0 = *(const float2*)(xr0 + (size_t)(t + 1) * 4);
            xq8 = *(const float2*)(xr8 + (size_t)(t + 1) * 4);
        }

        // ---- per unit-block j: 8 units x 16 batches ----
#pragma unroll 1
        for (int j = 0; j < 8; j++) {
            float dr[4] = {}, dz[4] = {}, dn[4] = {}, dx[4] = {};
            const ulonglong2* Br = BB + (j * 4) * 32 + lane;
            const ulonglong2* Bz = BB + ((8 + j) * 4) * 32 + lane;
            const ulonglong2* Bn = BB + ((16 + j) * 4) * 32 + lane;
#pragma unroll
            for (int kt = 0; kt < 4; kt++) {
                ulonglong2 br = Br[kt * 32], bz = Bz[kt * 32], bn = Bn[kt * 32];
                mma16(dr, Ahi[kt], LO32(br.x), HI32(br.x));
                mma16(dz, Ahi[kt], LO32(bz.x), HI32(bz.x));
                mma16(dn, Ahi[kt], LO32(bn.x), HI32(bn.x));
                mma16(dr, Alo[kt], LO32(br.x), HI32(br.x));
                mma16(dz, Alo[kt], LO32(bz.x), HI32(bz.x));
                mma16(dn, Alo[kt], LO32(bn.x), HI32(bn.x));
                mma16(dr, Ahi[kt], LO32(br.y), HI32(br.y));
                mma16(dz, Ahi[kt], LO32(bz.y), HI32(bz.y));
                mma16(dn, Ahi[kt], LO32(bn.y), HI32(bn.y));
            }
            {   // x contributions (hi/lo folded inside the k16 tile)
                uint64_t bxr = BX[j * 32 + lane];
                uint64_t bxz = BX[(8 + j) * 32 + lane];
                uint64_t bxn = BXN[j * 32 + lane];
                mma16(dr, Ax, LO32(bxr), HI32(bxr));
                mma16(dz, Ax, LO32(bxz), HI32(bxz));
                mma16(dx, Ax, LO32(bxn), HI32(bxn));
            }
            // ---- epilogue: units j*8+u0, +1; rows g and g+8 ----
            float2 b_r = *(const float2*)(BRZ + j * 8 + u0);
            float2 b_z = *(const float2*)(BRZ + 64 + j * 8 + u0);
            float2 b_h = *(const float2*)(BNH + j * 8 + u0);
            float2 b_x = *(const float2*)(BNX + j * 8 + u0);
            float* ha = hs + g * HP + j * 8 + u0;
            float* hb = ha + 8 * HP;
            float2 hoa = *(const float2*)ha;
            float2 hob = *(const float2*)hb;
            float hn0, hn1, hn2, hn3;
            {
                float r = sigf(dr[0] + b_r.x), z = sigf(dz[0] + b_z.x);
                float n = tanhf_fast(fmaf(r, dn[0] + b_h.x, dx[0] + b_x.x));
                hn0 = fmaf(z, hoa.x - n, n);
            }
            {
                float r = sigf(dr[1] + b_r.y), z = sigf(dz[1] + b_z.y);
                float n = tanhf_fast(fmaf(r, dn[1] + b_h.y, dx[1] + b_x.y));
                hn1 = fmaf(z, hoa.y - n, n);
            }
            {
                float r = sigf(dr[2] + b_r.x), z = sigf(dz[2] + b_z.x);
                float n = tanhf_fast(fmaf(r, dn[2] + b_h.x, dx[2] + b_x.x));
                hn2 = fmaf(z, hob.x - n, n);
            }
            {
                float r = sigf(dr[3] + b_r.y), z = sigf(dz[3] + b_z.y);
                float n = tanhf_fast(fmaf(r, dn[3] + b_h.y, dx[3] + b_x.y));
                hn3 = fmaf(z, hob.y - n, n);
            }
            *(float2*)ha = make_float2(hn0, hn1);
            *(float2*)hb = make_float2(hn2, hn3);
        }
        __syncwarp();
    }

    // ---- output ----
    for (int idx = lane; idx < 16 * 16; idx += 32) {
        int b = idx >> 4, q = idx & 15;
        float4 v = *(const float4*)(hs + b * HP + q * 4);
        ((float4*)out)[(size_t)(base + b) * 16 + q] = v;
    }
}

extern "C" void kernel_launch(void* const* d_in, const int* in_sizes, int n_in,
                              void* d_out, int out_size)
{
    const float* x    = (const float*)d_in[0];
    const float* w_ih = (const float*)d_in[1];
    const float* w_hh = (const float*)d_in[2];
    const float* b_ih = (const float*)d_in[3];
    const float* b_hh = (const float*)d_in[4];
    float* out = (float*)d_out;

    cudaFuncSetAttribute(gru_bmma, cudaFuncAttributeMaxDynamicSharedMemorySize, SMEM_TOTAL);
    gru_bmma<<<128, THREADS, SMEM_TOTAL>>>(x, w_ih, w_hh, b_ih, b_hh, out);
}

// round 7
// speedup vs baseline: 2.6913x; 1.1202x over previous
#include <cuda_runtime.h>
#include <cuda_bf16.h>
#include <cstdint>

// EncoderGRU B=16384 T=512 I=4 H=64 — bf16 m16n8k16 mma.sync, warp-pair split.
// 128 CTAs x 512 thr (16 warps = 4/SMSP). A warp PAIR owns 16 batches; each
// warp handles half the unit space (j-blocks 0..3 / 4..7 => 156 MMAs/warp-step).
// h double-buffered in smem; one named bar.sync(64) per pair per step.
// 3-term bf16 split (AhiBhi+AloBhi+AhiBlo), fp32 accum; x folded as one k16 tile.

#define T_STEPS 512
#define THREADS 512
#define HP 72   // h row stride (floats)

#define OFF_BB   0u        // ulonglong2[24 nt][4 kt][32]  49152
#define OFF_BX   49152u    // u64[16 nt][32]                4096
#define OFF_BXN  53248u    // u64[8 nt][32]                 2048
#define OFF_HS   55296u    // float[8 pairs][2 bufs][16][HP] 73728
#define OFF_BRZ  129024u   // float[128]
#define OFF_BNH  129536u   // float[64]
#define OFF_BNX  129792u   // float[64]
#define SMEM_TOTAL 130048

#define LO32(u) ((uint32_t)(u))
#define HI32(u) ((uint32_t)((u) >> 32))

__device__ __forceinline__ uint32_t pkb(__nv_bfloat16 a, __nv_bfloat16 b) {
    return (uint32_t)*(uint16_t*)&a | ((uint32_t)*(uint16_t*)&b << 16);
}
__device__ __forceinline__ void bsplit2(float a, float b, uint32_t& hi, uint32_t& lo) {
    __nv_bfloat16 ah = __float2bfloat16_rn(a), bh = __float2bfloat16_rn(b);
    __nv_bfloat16 al = __float2bfloat16_rn(a - __bfloat162float(ah));
    __nv_bfloat16 bl = __float2bfloat16_rn(b - __bfloat162float(bh));
    hi = pkb(ah, bh);
    lo = pkb(al, bl);
}
__device__ __forceinline__ void mma16(float* d, const uint32_t* a, uint32_t b0, uint32_t b1) {
    asm("mma.sync.aligned.m16n8k16.row.col.f32.bf16.bf16.f32 "
        "{%0,%1,%2,%3}, {%4,%5,%6,%7}, {%8,%9}, {%0,%1,%2,%3};"
        : "+f"(d[0]), "+f"(d[1]), "+f"(d[2]), "+f"(d[3])
        : "r"(a[0]), "r"(a[1]), "r"(a[2]), "r"(a[3]), "r"(b0), "r"(b1));
}
__device__ __forceinline__ float sigf(float x) {
    return __fdividef(1.0f, 1.0f + __expf(-x));
}
__device__ __forceinline__ float tanhf_fast(float x) {
    return 1.0f - __fdividef(2.0f, __expf(2.0f * x) + 1.0f);
}

__global__ __launch_bounds__(THREADS, 1)
void gru_bmma2(const float* __restrict__ x, const float* __restrict__ w_ih,
               const float* __restrict__ w_hh, const float* __restrict__ b_ih,
               const float* __restrict__ b_hh, float* __restrict__ out)
{
    extern __shared__ char sm[];
    ulonglong2* BB  = (ulonglong2*)(sm + OFF_BB);
    uint64_t*   BX  = (uint64_t*)(sm + OFF_BX);
    uint64_t*   BXN = (uint64_t*)(sm + OFF_BXN);
    float* HS  = (float*)(sm + OFF_HS);
    float* BRZ = (float*)(sm + OFF_BRZ);
    float* BNH = (float*)(sm + OFF_BNH);
    float* BNX = (float*)(sm + OFF_BNX);

    const int tid = threadIdx.x, lane = tid & 31, warp = tid >> 5;

    // ================= one-time init =================
    for (int idx = tid; idx < 24 * 4 * 32; idx += THREADS) {
        int nt = idx >> 7, kt = (idx >> 5) & 3, le = idx & 31;
        int n = nt * 8 + (le >> 2), k0 = kt * 16 + 2 * (le & 3);
        uint32_t h01, l01, h89, l89;
        bsplit2(w_hh[n * 64 + k0],     w_hh[n * 64 + k0 + 1], h01, l01);
        bsplit2(w_hh[n * 64 + k0 + 8], w_hh[n * 64 + k0 + 9], h89, l89);
        BB[idx].x = (uint64_t)h01 | ((uint64_t)h89 << 32);
        BB[idx].y = (uint64_t)l01 | ((uint64_t)l89 << 32);
    }
    for (int idx = tid; idx < 16 * 32; idx += THREADS) {
        int nt = idx >> 5, le = idx & 31, c = le & 3;
        int n = nt * 8 + (le >> 2), cc = 2 * (c & 1);
        uint32_t hi, lo;
        bsplit2(w_ih[n * 4 + cc], w_ih[n * 4 + cc + 1], hi, lo);
        BX[idx] = (uint64_t)hi | ((uint64_t)((c < 2) ? lo : 0u) << 32);
    }
    for (int idx = tid; idx < 8 * 32; idx += THREADS) {
        int nt = idx >> 5, le = idx & 31, c = le & 3;
        int n = 128 + nt * 8 + (le >> 2), cc = 2 * (c & 1);
        uint32_t hi, lo;
        bsplit2(w_ih[n * 4 + cc], w_ih[n * 4 + cc + 1], hi, lo);
        BXN[idx] = (uint64_t)hi | ((uint64_t)((c < 2) ? lo : 0u) << 32);
    }
    for (int idx = tid; idx < 8 * 2 * 16 * HP; idx += THREADS) HS[idx] = 0.0f;
    for (int idx = tid; idx < 128; idx += THREADS) BRZ[idx] = b_ih[idx] + b_hh[idx];
    if (tid < 64) { BNH[tid] = b_hh[128 + tid]; BNX[tid] = b_ih[128 + tid]; }
    __syncthreads();

    // ================= per-warp geometry =================
    const int pair = warp >> 1, half = warp & 1;
    const int base = (blockIdx.x * 8 + pair) * 16;
    float* hs0 = HS + pair * (2 * 16 * HP);            // buf0 slab
    const int g = lane >> 2, c = lane & 3;
    const int u0 = 2 * c, cc = 2 * (c & 1);
    const int j0 = half * 4;                           // this warp's unit-blocks

    const float* __restrict__ xr0 = x + ((size_t)(base + g) * T_STEPS) * 4 + cc;
    const float* __restrict__ xr8 = x + ((size_t)(base + g + 8) * T_STEPS) * 4 + cc;
    float2 xq0 = *(const float2*)xr0;
    float2 xq8 = *(const float2*)xr8;

    uint32_t Ahi[4][4], Alo[4][4], Ax[4];

    for (int t = 0; t < T_STEPS; t++) {
        float* hrd = hs0 + (t & 1) * (16 * HP);
        float* hwr = hs0 + ((t & 1) ^ 1) * (16 * HP);

        // ---- A frags from h smem (both warps duplicate; cheap) ----
#pragma unroll
        for (int kt = 0; kt < 4; kt++) {
            const float* r0 = hrd + g * HP + kt * 16 + u0;
            const float* r8 = r0 + 8 * HP;
            float2 v0 = *(const float2*)r0;
            float2 v8 = *(const float2*)r8;
            float2 w0 = *(const float2*)(r0 + 8);
            float2 w8 = *(const float2*)(r8 + 8);
            bsplit2(v0.x, v0.y, Ahi[kt][0], Alo[kt][0]);
            bsplit2(v8.x, v8.y, Ahi[kt][1], Alo[kt][1]);
            bsplit2(w0.x, w0.y, Ahi[kt][2], Alo[kt][2]);
            bsplit2(w8.x, w8.y, Ahi[kt][3], Alo[kt][3]);
        }
        {   // x frag: A cols [xhi(4)|xlo(4)|xhi(4)|0(4)]
            uint32_t xh0, xl0, xh8, xl8;
            bsplit2(xq0.x, xq0.y, xh0, xl0);
            bsplit2(xq8.x, xq8.y, xh8, xl8);
            Ax[0] = (c < 2) ? xh0 : xl0;
            Ax[1] = (c < 2) ? xh8 : xl8;
            Ax[2] = (c < 2) ? xh0 : 0u;
            Ax[3] = (c < 2) ? xh8 : 0u;
        }
        if (t + 1 < T_STEPS) {   // prefetch under MMA latency
            xq0 = *(const float2*)(xr0 + (size_t)(t + 1) * 4);
            xq8 = *(const float2*)(xr8 + (size_t)(t + 1) * 4);
        }

        // ---- this warp's 4 unit-blocks ----
#pragma unroll 1
        for (int jj = 0; jj < 4; jj++) {
            const int j = j0 + jj;
            float dr[4] = {}, dz[4] = {}, dn[4] = {}, dx[4] = {};
            const ulonglong2* Br = BB + (j * 4) * 32 + lane;
            const ulonglong2* Bz = BB + ((8 + j) * 4) * 32 + lane;
            const ulonglong2* Bn = BB + ((16 + j) * 4) * 32 + lane;
#pragma unroll
            for (int kt = 0; kt < 4; kt++) {
                ulonglong2 br = Br[kt * 32], bz = Bz[kt * 32], bn = Bn[kt * 32];
                mma16(dr, Ahi[kt], LO32(br.x), HI32(br.x));
                mma16(dz, Ahi[kt], LO32(bz.x), HI32(bz.x));
                mma16(dn, Ahi[kt], LO32(bn.x), HI32(bn.x));
                mma16(dr, Alo[kt], LO32(br.x), HI32(br.x));
                mma16(dz, Alo[kt], LO32(bz.x), HI32(bz.x));
                mma16(dn, Alo[kt], LO32(bn.x), HI32(bn.x));
                mma16(dr, Ahi[kt], LO32(br.y), HI32(br.y));
                mma16(dz, Ahi[kt], LO32(bz.y), HI32(bz.y));
                mma16(dn, Ahi[kt], LO32(bn.y), HI32(bn.y));
            }
            {
                uint64_t bxr = BX[j * 32 + lane];
                uint64_t bxz = BX[(8 + j) * 32 + lane];
                uint64_t bxn = BXN[j * 32 + lane];
                mma16(dr, Ax, LO32(bxr), HI32(bxr));
                mma16(dz, Ax, LO32(bxz), HI32(bxz));
                mma16(dx, Ax, LO32(bxn), HI32(bxn));
            }
            // ---- epilogue: units j*8+u0, +1; rows g, g+8 (own units only) ----
            float2 b_r = *(const float2*)(BRZ + j * 8 + u0);
            float2 b_z = *(const float2*)(BRZ + 64 + j * 8 + u0);
            float2 b_h = *(const float2*)(BNH + j * 8 + u0);
            float2 b_x = *(const float2*)(BNX + j * 8 + u0);
            const float* ha = hrd + g * HP + j * 8 + u0;
            const float* hb = ha + 8 * HP;
            float2 hoa = *(const float2*)ha;
            float2 hob = *(const float2*)hb;
            float hn0, hn1, hn2, hn3;
            {
                float r = sigf(dr[0] + b_r.x), z = sigf(dz[0] + b_z.x);
                float n = tanhf_fast(fmaf(r, dn[0] + b_h.x, dx[0] + b_x.x));
                hn0 = fmaf(z, hoa.x - n, n);
            }
            {
                float r = sigf(dr[1] + b_r.y), z = sigf(dz[1] + b_z.y);
                float n = tanhf_fast(fmaf(r, dn[1] + b_h.y, dx[1] + b_x.y));
                hn1 = fmaf(z, hoa.y - n, n);
            }
            {
                float r = sigf(dr[2] + b_r.x), z = sigf(dz[2] + b_z.x);
                float n = tanhf_fast(fmaf(r, dn[2] + b_h.x, dx[2] + b_x.x));
                hn2 = fmaf(z, hob.x - n, n);
            }
            {
                float r = sigf(dr[3] + b_r.y), z = sigf(dz[3] + b_z.y);
                float n = tanhf_fast(fmaf(r, dn[3] + b_h.y, dx[3] + b_x.y));
                hn3 = fmaf(z, hob.y - n, n);
            }
            float* wa = hwr + g * HP + j * 8 + u0;
            *(float2*)wa            = make_float2(hn0, hn1);
            *(float2*)(wa + 8 * HP) = make_float2(hn2, hn3);
        }

        // pair-scoped barrier: orders this step's h' writes before next step's reads
        asm volatile("bar.sync %0, %1;" :: "r"(pair + 1), "r"(64) : "memory");
    }

    // ---- output: final h in buf[T_STEPS & 1] = buf0; warp writes its 32 units ----
    const float* hfin = hs0 + (T_STEPS & 1) * (16 * HP);
    for (int idx = lane; idx < 16 * 8; idx += 32) {
        int b = idx >> 3, q = idx & 7;                 // q: float4 index within 32 units
        float4 v = *(const float4*)(hfin + b * HP + half * 32 + q * 4);
        ((float4*)out)[(size_t)(base + b) * 16 + half * 8 + q] = v;
    }
}

extern "C" void kernel_launch(void* const* d_in, const int* in_sizes, int n_in,
                              void* d_out, int out_size)
{
    const float* x    = (const float*)d_in[0];
    const float* w_ih = (const float*)d_in[1];
    const float* w_hh = (const float*)d_in[2];
    const float* b_ih = (const float*)d_in[3];
    const float* b_hh = (const float*)d_in[4];
    float* out = (float*)d_out;

    cudaFuncSetAttribute(gru_bmma2, cudaFuncAttributeMaxDynamicSharedMemorySize, SMEM_TOTAL);
    gru_bmma2<<<128, THREADS, SMEM_TOTAL>>>(x, w_ih, w_hh, b_ih, b_hh, out);
}